// round 1
// baseline (speedup 1.0000x reference)
#include <cuda_runtime.h>
#include <math.h>

// Problem constants
#define B_    16
#define CIN   384
#define L0    65536   // B * 64*64
#define L1    16384   // B * 32*32
#define N0_   4096
#define N1_   1024
#define CDIM_ 128
#define KK_   64

// -------- scratch (device globals; no allocation allowed) --------
__device__ float g_xt  [CIN * L0];        // x transposed to [C, B*N0]
__device__ float g_x1t [CIN * L1];        // pooled x transposed [C, B*N1]
__device__ float g_hidden[1152 * L0];     // relu(hidden) rows: f[0..512) s[512..1024) d[1024..1152)
__device__ float g_feat[CDIM_ * L0];      // local_feat [128, L]
__device__ float g_Z   [65 * L0];         // scores+dustbin, later overwritten with P (rows 0..63)
__device__ float g_out [2 * B_ * CDIM_ * KK_]; // per-scale einsum outputs

__device__ __forceinline__ float* bufptr(int id) {
    switch (id) {
        case 0: return g_xt;
        case 1: return g_x1t;
        case 2: return g_hidden;
        case 3: return g_feat;
        default: return g_Z;
    }
}

// -------- layout transforms --------
__global__ void transpose_k(const float* __restrict__ x) {
    int idx = blockIdx.x * 256 + threadIdx.x;           // total 384*65536
    int c = idx >> 16;
    int l = idx & 65535;
    int b = l >> 12;
    int n = l & 4095;
    g_xt[idx] = x[((long)(b * CIN + c) << 12) + n];
}

__global__ void pool_k(const float* __restrict__ x) {
    int idx = blockIdx.x * 256 + threadIdx.x;           // total 384*16384
    int c = idx >> 14;
    int l = idx & 16383;
    int b = l >> 10;
    int p = l & 1023;
    int i = p >> 5, j = p & 31;
    const float* xb = x + ((long)(b * CIN + c) << 12);
    int r0 = (2 * i) * 64 + 2 * j;
    g_x1t[idx] = 0.25f * (xb[r0] + xb[r0 + 1] + xb[r0 + 64] + xb[r0 + 65]);
}

__global__ void zero_k() {
    int i = blockIdx.x * 256 + threadIdx.x;
    if (i < 2 * B_ * CDIM_ * KK_) g_out[i] = 0.f;
}

// -------- fp32 SGEMM: C[M,L] = W[M,K] @ X[K,L] (+bias, opt relu) --------
// 128x128 tile, BK=16, 256 threads, 8x8 per thread (4+4 split layout).
template <bool RELU>
__global__ void __launch_bounds__(256)
sgemm(const float* __restrict__ W, const float* __restrict__ bias,
      int xid, long xoff, int cid, long coff, int M, int K, int L) {
    const float* X = bufptr(xid) + xoff;
    float* C = bufptr(cid) + coff;

    __shared__ float As[16][132];
    __shared__ float Bs[16][132];

    int tid = threadIdx.x;
    int tx = tid & 15, ty = tid >> 4;
    int bm = blockIdx.y * 128, bl = blockIdx.x * 128;

    float acc[8][8];
#pragma unroll
    for (int i = 0; i < 8; i++)
#pragma unroll
        for (int j = 0; j < 8; j++) acc[i][j] = 0.f;

    for (int kt = 0; kt < K; kt += 16) {
#pragma unroll
        for (int i = 0; i < 8; i++) {
            int e = tid + i * 256;
            int m = e >> 4, k = e & 15;
            float v = 0.f;
            if (bm + m < M) v = W[(long)(bm + m) * K + kt + k];
            As[k][m] = v;
        }
#pragma unroll
        for (int i = 0; i < 8; i++) {
            int e = tid + i * 256;
            int k = e >> 7, n = e & 127;
            Bs[k][n] = X[(long)(kt + k) * L + bl + n];
        }
        __syncthreads();
#pragma unroll
        for (int k = 0; k < 16; k++) {
            float a[8], bb[8];
            float4 t;
            t = *(const float4*)&As[k][ty * 4];      a[0]=t.x; a[1]=t.y; a[2]=t.z; a[3]=t.w;
            t = *(const float4*)&As[k][ty * 4 + 64]; a[4]=t.x; a[5]=t.y; a[6]=t.z; a[7]=t.w;
            t = *(const float4*)&Bs[k][tx * 4];      bb[0]=t.x; bb[1]=t.y; bb[2]=t.z; bb[3]=t.w;
            t = *(const float4*)&Bs[k][tx * 4 + 64]; bb[4]=t.x; bb[5]=t.y; bb[6]=t.z; bb[7]=t.w;
#pragma unroll
            for (int i = 0; i < 8; i++)
#pragma unroll
                for (int j = 0; j < 8; j++) acc[i][j] += a[i] * bb[j];
        }
        __syncthreads();
    }

#pragma unroll
    for (int i = 0; i < 8; i++) {
        int r = bm + ((i < 4) ? (ty * 4 + i) : (64 + ty * 4 + i - 4));
        if (r >= M) continue;
        float bv = bias[r];
#pragma unroll
        for (int jh = 0; jh < 2; jh++) {
            int c0 = bl + tx * 4 + jh * 64;
            float4 v;
            float* av = &acc[i][jh * 4];
            v.x = av[0] + bv; v.y = av[1] + bv; v.z = av[2] + bv; v.w = av[3] + bv;
            if (RELU) {
                v.x = fmaxf(v.x, 0.f); v.y = fmaxf(v.y, 0.f);
                v.z = fmaxf(v.z, 0.f); v.w = fmaxf(v.w, 0.f);
            }
            *(float4*)&C[(long)r * L + c0] = v;
        }
    }
}

// -------- dustbin: Z[64, l] = db2 + dw2[128] . hidden[1024+k][l] --------
__global__ void dustbin_k(const float* __restrict__ dw2, const float* __restrict__ db2, int L) {
    __shared__ float w[128];
    int tid = threadIdx.x;
    if (tid < 128) w[tid] = dw2[tid];
    __syncthreads();
    long l = (long)blockIdx.x * 256 + tid;
    const float* h = g_hidden + (long)1024 * L + l;
    float acc = db2[0];
#pragma unroll 8
    for (int k = 0; k < 128; k++) acc += w[k] * h[(long)k * L];
    g_Z[(long)64 * L + l] = acc;
}

// -------- Sinkhorn (3 iters) + unnormalized P write (rows 0..63) --------
__global__ void __launch_bounds__(1024) sinkhorn_k(int N, int L) {
    int b = blockIdx.x;
    __shared__ float v[4096];
    __shared__ float u[72];
    int tid = threadIdx.x;
    int lane = tid & 31, warp = tid >> 5;
    const float NEG_INF = -INFINITY;
    float log_mu = -logf(65.0f);
    float log_nu = -logf((float)N);
    long zb = (long)b * N;

    for (int n = tid; n < N; n += 1024) v[n] = 0.f;
    if (tid < 72) u[tid] = 0.f;
    __syncthreads();

    for (int it = 0; it < 3; it++) {
        // u-step: one warp per row k
        for (int k = warp; k < 65; k += 32) {
            float m = NEG_INF, s = 0.f;
            const float* zr = g_Z + (long)k * L + zb;
            for (int n = lane; n < N; n += 32) {
                float val = zr[n] + v[n];
                if (val > m) { s = s * __expf(m - val) + 1.f; m = val; }
                else          s += __expf(val - m);
            }
#pragma unroll
            for (int off = 16; off; off >>= 1) {
                float m2 = __shfl_xor_sync(0xffffffffu, m, off);
                float s2 = __shfl_xor_sync(0xffffffffu, s, off);
                if (m2 > m) { s = s * __expf(m - m2) + s2; m = m2; }
                else if (m2 > NEG_INF) s += s2 * __expf(m2 - m);
            }
            if (lane == 0) u[k] = log_mu - (m + __logf(s));
        }
        __syncthreads();
        // v-step: one thread per column n
        for (int n = tid; n < N; n += 1024) {
            float m = NEG_INF, s = 0.f;
            for (int k = 0; k < 65; k++) {
                float val = g_Z[(long)k * L + zb + n] + u[k];
                if (val > m) { s = s * __expf(m - val) + 1.f; m = val; }
                else          s += __expf(val - m);
            }
            v[n] = log_nu - (m + __logf(s));
        }
        __syncthreads();
    }
    // P = exp(Z + u + v), rows 0..63, written in-place over Z
    for (int k = 0; k < 64; k++) {
        float uk = u[k];
        float* zr = g_Z + (long)k * L + zb;
        for (int n = tid; n < N; n += 1024) zr[n] = __expf(zr[n] + uk + v[n]);
    }
}

// -------- einsum: out[b,c,k] += sum_n feat[c,n] * P[k,n], split over n --------
__global__ void __launch_bounds__(256) einsum_k(int scale, int N, int L) {
    int b = blockIdx.x;
    int nc0 = blockIdx.y * 128;
    __shared__ float Fs[32][132];
    __shared__ float Ps[32][68];
    int tid = threadIdx.x, tx = tid & 15, ty = tid >> 4;
    long base = (long)b * N;

    float acc[8][4];
#pragma unroll
    for (int i = 0; i < 8; i++)
#pragma unroll
        for (int j = 0; j < 4; j++) acc[i][j] = 0.f;

    for (int nc = nc0; nc < nc0 + 128; nc += 32) {
#pragma unroll
        for (int i = 0; i < 16; i++) {
            int e = tid + i * 256;
            int c = e >> 5, n = e & 31;
            Fs[n][c] = g_feat[(long)c * L + base + nc + n];
        }
#pragma unroll
        for (int i = 0; i < 8; i++) {
            int e = tid + i * 256;
            int k = e >> 5, n = e & 31;
            Ps[n][k] = g_Z[(long)k * L + base + nc + n];
        }
        __syncthreads();
#pragma unroll
        for (int kk = 0; kk < 32; kk++) {
            float a[8], bb[4];
            float4 t;
            t = *(const float4*)&Fs[kk][ty * 4];      a[0]=t.x; a[1]=t.y; a[2]=t.z; a[3]=t.w;
            t = *(const float4*)&Fs[kk][ty * 4 + 64]; a[4]=t.x; a[5]=t.y; a[6]=t.z; a[7]=t.w;
            t = *(const float4*)&Ps[kk][tx * 4];      bb[0]=t.x; bb[1]=t.y; bb[2]=t.z; bb[3]=t.w;
#pragma unroll
            for (int i = 0; i < 8; i++)
#pragma unroll
                for (int j = 0; j < 4; j++) acc[i][j] += a[i] * bb[j];
        }
        __syncthreads();
    }

    float* outp = g_out + ((long)scale * B_ + b) * (CDIM_ * KK_);
#pragma unroll
    for (int i = 0; i < 8; i++) {
        int r = (i < 4) ? (ty * 4 + i) : (64 + ty * 4 + i - 4);
#pragma unroll
        for (int j = 0; j < 4; j++)
            atomicAdd(&outp[r * 64 + tx * 4 + j], acc[i][j]);
    }
}

// -------- final: per-scale column L2 norm, average, global L2 norm --------
__global__ void __launch_bounds__(256) final_k(float* __restrict__ out) {
    int b = blockIdx.x, tid = threadIdx.x;
    __shared__ float d[8192];
    __shared__ float cn[2][64];
    __shared__ float red[9];
    if (tid < 128) cn[tid >> 6][tid & 63] = 0.f;
    __syncthreads();
    const float* o0 = g_out + (long)b * 8192;
    const float* o1 = g_out + (long)(B_ + b) * 8192;
    for (int e = tid; e < 8192; e += 256) {
        float v0 = o0[e], v1 = o1[e];
        atomicAdd(&cn[0][e & 63], v0 * v0);
        atomicAdd(&cn[1][e & 63], v1 * v1);
    }
    __syncthreads();
    if (tid < 128) {
        float nn = sqrtf(cn[tid >> 6][tid & 63]);
        cn[tid >> 6][tid & 63] = 1.f / fmaxf(nn, 1e-12f);
    }
    __syncthreads();
    float ss = 0.f;
    for (int e = tid; e < 8192; e += 256) {
        int k = e & 63;
        float dv = 0.5f * (o0[e] * cn[0][k] + o1[e] * cn[1][k]);
        d[e] = dv;
        ss += dv * dv;
    }
#pragma unroll
    for (int off = 16; off; off >>= 1) ss += __shfl_xor_sync(0xffffffffu, ss, off);
    if ((tid & 31) == 0) red[tid >> 5] = ss;
    __syncthreads();
    if (tid == 0) {
        float t = 0.f;
        for (int i = 0; i < 8; i++) t += red[i];
        red[8] = 1.f / fmaxf(sqrtf(t), 1e-12f);
    }
    __syncthreads();
    float inv = red[8];
    for (int e = tid; e < 8192; e += 256) out[(long)b * 8192 + e] = d[e] * inv;
}

extern "C" void kernel_launch(void* const* d_in, const int* in_sizes, int n_in,
                              void* d_out, int out_size) {
    (void)in_sizes; (void)n_in; (void)out_size;
    const float* x = (const float*)d_in[0];

    zero_k<<<1024, 256>>>();
    transpose_k<<<(CIN * L0) / 256, 256>>>(x);
    pool_k<<<(CIN * L1) / 256, 256>>>(x);

    for (int s = 0; s < 2; s++) {
        int base = 1 + s * 12;
        const float* fw1 = (const float*)d_in[base + 0];
        const float* fb1 = (const float*)d_in[base + 1];
        const float* fw2 = (const float*)d_in[base + 2];
        const float* fb2 = (const float*)d_in[base + 3];
        const float* sw1 = (const float*)d_in[base + 4];
        const float* sb1 = (const float*)d_in[base + 5];
        const float* sw2 = (const float*)d_in[base + 6];
        const float* sb2 = (const float*)d_in[base + 7];
        const float* dw1 = (const float*)d_in[base + 8];
        const float* db1 = (const float*)d_in[base + 9];
        const float* dw2 = (const float*)d_in[base + 10];
        const float* db2 = (const float*)d_in[base + 11];

        int L = s ? L1 : L0;
        int N = s ? N1_ : N0_;
        int xid = s ? 1 : 0;

        // layer 1 (relu): rows [0,512) f, [512,1024) s, [1024,1152) d
        sgemm<true><<<dim3(L / 128, 4), 256>>>(fw1, fb1, xid, 0L, 2, 0L, 512, CIN, L);
        sgemm<true><<<dim3(L / 128, 4), 256>>>(sw1, sb1, xid, 0L, 2, (long)512 * L, 512, CIN, L);
        sgemm<true><<<dim3(L / 128, 1), 256>>>(dw1, db1, xid, 0L, 2, (long)1024 * L, 128, CIN, L);
        // layer 2
        sgemm<false><<<dim3(L / 128, 1), 256>>>(fw2, fb2, 2, 0L, 3, 0L, CDIM_, 512, L);
        sgemm<false><<<dim3(L / 128, 1), 256>>>(sw2, sb2, 2, (long)512 * L, 4, 0L, KK_, 512, L);
        dustbin_k<<<L / 256, 256>>>(dw2, db2, L);

        sinkhorn_k<<<B_, 1024>>>(N, L);
        einsum_k<<<dim3(B_, N / 128), 256>>>(s, N, L);
    }

    final_k<<<B_, 256>>>((float*)d_out);
}

// round 2
// speedup vs baseline: 2.2778x; 2.2778x over previous
#include <cuda_runtime.h>
#include <math.h>

// Problem constants
#define B_    16
#define CIN   384
#define L0    65536   // B * 64*64
#define L1    16384   // B * 32*32
#define N0_   4096
#define N1_   1024
#define CDIM_ 128
#define KK_   64
#define BK    16

// -------- scratch (device globals; no allocation allowed) --------
__device__ float g_xt  [CIN * L0];        // x transposed to [C, B*N0]
__device__ float g_x1t [CIN * L1];        // pooled x transposed [C, B*N1]
__device__ float g_hidden[1152 * L0];     // relu(hidden): f[0..512) s[512..1024) d[1024..1152)
__device__ float g_feat[CDIM_ * L0];      // local_feat [128, L]
__device__ float g_Z   [65 * L0];         // scores+dustbin, later P (rows 0..63)
__device__ float g_out [2 * B_ * CDIM_ * KK_];
__device__ float g_w1  [1152 * CIN];      // concatenated layer-1 weights
__device__ float g_b1  [1152];

__device__ __forceinline__ float* bufptr(int id) {
    switch (id) {
        case 0: return g_xt;
        case 1: return g_x1t;
        case 2: return g_hidden;
        case 3: return g_feat;
        case 4: return g_Z;
        case 5: return g_w1;
        default: return g_b1;
    }
}

// -------- layout transforms --------
__global__ void transpose_k(const float* __restrict__ x) {
    int idx = blockIdx.x * 256 + threadIdx.x;
    int c = idx >> 16;
    int l = idx & 65535;
    int b = l >> 12;
    int n = l & 4095;
    g_xt[idx] = x[((long)(b * CIN + c) << 12) + n];
}

__global__ void pool_k(const float* __restrict__ x) {
    int idx = blockIdx.x * 256 + threadIdx.x;
    int c = idx >> 14;
    int l = idx & 16383;
    int b = l >> 10;
    int p = l & 1023;
    int i = p >> 5, j = p & 31;
    const float* xb = x + ((long)(b * CIN + c) << 12);
    int r0 = (2 * i) * 64 + 2 * j;
    g_x1t[idx] = 0.25f * (xb[r0] + xb[r0 + 1] + xb[r0 + 64] + xb[r0 + 65]);
}

__global__ void zero_k() {
    int i = blockIdx.x * 256 + threadIdx.x;
    if (i < 2 * B_ * CDIM_ * KK_) g_out[i] = 0.f;
}

// concat fw1/sw1/dw1 -> g_w1, biases -> g_b1
__global__ void concat1_k(const float* __restrict__ fw1, const float* __restrict__ fb1,
                          const float* __restrict__ sw1, const float* __restrict__ sb1,
                          const float* __restrict__ dw1, const float* __restrict__ db1) {
    int idx = blockIdx.x * 256 + threadIdx.x;
    const int W1 = 512 * CIN, W2 = 1024 * CIN, WT = 1152 * CIN;
    if (idx < WT) {
        float v;
        if (idx < W1) v = fw1[idx];
        else if (idx < W2) v = sw1[idx - W1];
        else v = dw1[idx - W2];
        g_w1[idx] = v;
        if (idx < 1152)
            g_b1[idx] = (idx < 512) ? fb1[idx] : (idx < 1024) ? sb1[idx - 512] : db1[idx - 1024];
    }
}

// -------- cp.async helpers --------
__device__ __forceinline__ void cp_async16(void* smem, const void* gmem, bool pred) {
    unsigned saddr = (unsigned)__cvta_generic_to_shared(smem);
    int sz = pred ? 16 : 0;
    asm volatile("cp.async.cg.shared.global [%0], [%1], 16, %2;\n"
                 :: "r"(saddr), "l"(gmem), "r"(sz));
}
__device__ __forceinline__ void cp_commit() { asm volatile("cp.async.commit_group;\n"); }
__device__ __forceinline__ void cp_wait0()  { asm volatile("cp.async.wait_group 0;\n"); }
__device__ __forceinline__ void cp_wait1()  { asm volatile("cp.async.wait_group 1;\n"); }

__device__ __forceinline__ unsigned f2tf32(float x) {
    unsigned u;
    asm("cvt.rna.tf32.f32 %0, %1;\n" : "=r"(u) : "f"(x));
    return u;
}

// -------- tf32 tensor-core GEMM: C[M,L] = W[M,K] @ X[K,L] (+bias, opt relu) --------
// 128x128 tile, BK=16, 256 threads = 8 warps (4Mx2N), each warp 32Mx64N via m16n8k8.
// SMEM: A [128][20] (m-major), B [16][136] (k-major) — both conflict-free for frag loads.
template <bool RELU>
__global__ void __launch_bounds__(256)
tgemm(const float* __restrict__ Wp, const float* __restrict__ biasp,
      int xid, long xoff, int cid, long coff, int M, int K, int L) {
    const float* W    = Wp    ? Wp    : bufptr(5);
    const float* bias = biasp ? biasp : bufptr(6);
    const float* X = bufptr(xid) + xoff;
    float* C = bufptr(cid) + coff;

    __shared__ float sA[2][128 * 20];
    __shared__ float sB[2][16 * 136];

    int tid = threadIdx.x;
    int lane = tid & 31, warp = tid >> 5;
    int wm = warp >> 1, wn = warp & 1;
    int g = lane >> 2, tg = lane & 3;
    int bm = blockIdx.x * 128, bl = blockIdx.y * 128;

    float acc[2][8][4];
#pragma unroll
    for (int mt = 0; mt < 2; mt++)
#pragma unroll
        for (int nt = 0; nt < 8; nt++)
#pragma unroll
            for (int i = 0; i < 4; i++) acc[mt][nt][i] = 0.f;

    int ntiles = K / BK;

#define PREFETCH(kt, buf)                                                          \
    {                                                                              \
        _Pragma("unroll")                                                          \
        for (int i = 0; i < 2; i++) {                                              \
            int f = tid + i * 256;                                                 \
            int m = f >> 2, kq = f & 3;                                            \
            int r = bm + m;                                                        \
            bool p = r < M;                                                        \
            int rs = p ? r : (M - 1);                                              \
            cp_async16(&sA[buf][m * 20 + kq * 4],                                  \
                       W + (long)rs * K + (kt) * BK + kq * 4, p);                  \
        }                                                                          \
        _Pragma("unroll")                                                          \
        for (int i = 0; i < 2; i++) {                                              \
            int f = tid + i * 256;                                                 \
            int k = f >> 5, nq = f & 31;                                           \
            cp_async16(&sB[buf][k * 136 + nq * 4],                                 \
                       X + (long)((kt) * BK + k) * L + bl + nq * 4, true);         \
        }                                                                          \
        cp_commit();                                                               \
    }

    PREFETCH(0, 0);

    for (int kt = 0; kt < ntiles; kt++) {
        int buf = kt & 1;
        if (kt + 1 < ntiles) {
            PREFETCH(kt + 1, buf ^ 1);
            cp_wait1();
        } else {
            cp_wait0();
        }
        __syncthreads();

        const float* A = sA[buf];
        const float* Bm = sB[buf];
#pragma unroll
        for (int ks = 0; ks < 2; ks++) {
            int k0 = ks * 8;
            unsigned a[2][4];
#pragma unroll
            for (int mt = 0; mt < 2; mt++) {
                int m0 = wm * 32 + mt * 16 + g;
                a[mt][0] = f2tf32(A[m0 * 20 + k0 + tg]);
                a[mt][1] = f2tf32(A[(m0 + 8) * 20 + k0 + tg]);
                a[mt][2] = f2tf32(A[m0 * 20 + k0 + tg + 4]);
                a[mt][3] = f2tf32(A[(m0 + 8) * 20 + k0 + tg + 4]);
            }
            unsigned bfr[8][2];
#pragma unroll
            for (int nt = 0; nt < 8; nt++) {
                int n0 = wn * 64 + nt * 8 + g;
                bfr[nt][0] = f2tf32(Bm[(k0 + tg) * 136 + n0]);
                bfr[nt][1] = f2tf32(Bm[(k0 + tg + 4) * 136 + n0]);
            }
#pragma unroll
            for (int mt = 0; mt < 2; mt++)
#pragma unroll
                for (int nt = 0; nt < 8; nt++) {
                    asm volatile(
                        "mma.sync.aligned.m16n8k8.row.col.f32.tf32.tf32.f32 "
                        "{%0,%1,%2,%3}, {%4,%5,%6,%7}, {%8,%9}, {%0,%1,%2,%3};\n"
                        : "+f"(acc[mt][nt][0]), "+f"(acc[mt][nt][1]),
                          "+f"(acc[mt][nt][2]), "+f"(acc[mt][nt][3])
                        : "r"(a[mt][0]), "r"(a[mt][1]), "r"(a[mt][2]), "r"(a[mt][3]),
                          "r"(bfr[nt][0]), "r"(bfr[nt][1]));
                }
        }
        __syncthreads();
    }
#undef PREFETCH

    // epilogue: bias (+relu), float2 stores
#pragma unroll
    for (int mt = 0; mt < 2; mt++) {
        int r0 = bm + wm * 32 + mt * 16 + g;
        int r1 = r0 + 8;
        float bv0 = (r0 < M) ? bias[r0] : 0.f;
        float bv1 = (r1 < M) ? bias[r1] : 0.f;
#pragma unroll
        for (int nt = 0; nt < 8; nt++) {
            int cc = bl + wn * 64 + nt * 8 + tg * 2;
            if (r0 < M) {
                float2 v;
                v.x = acc[mt][nt][0] + bv0;
                v.y = acc[mt][nt][1] + bv0;
                if (RELU) { v.x = fmaxf(v.x, 0.f); v.y = fmaxf(v.y, 0.f); }
                *(float2*)&C[(long)r0 * L + cc] = v;
            }
            if (r1 < M) {
                float2 v;
                v.x = acc[mt][nt][2] + bv1;
                v.y = acc[mt][nt][3] + bv1;
                if (RELU) { v.x = fmaxf(v.x, 0.f); v.y = fmaxf(v.y, 0.f); }
                *(float2*)&C[(long)r1 * L + cc] = v;
            }
        }
    }
}

// -------- dustbin: Z[64, l] = db2 + dw2[128] . hidden[1024+k][l] --------
__global__ void dustbin_k(const float* __restrict__ dw2, const float* __restrict__ db2, int L) {
    __shared__ float w[128];
    int tid = threadIdx.x;
    if (tid < 128) w[tid] = dw2[tid];
    __syncthreads();
    long l = (long)blockIdx.x * 256 + tid;
    const float* h = g_hidden + (long)1024 * L + l;
    float acc = db2[0];
#pragma unroll 8
    for (int k = 0; k < 128; k++) acc += w[k] * h[(long)k * L];
    g_Z[(long)64 * L + l] = acc;
}

// -------- Sinkhorn (3 iters) + unnormalized P (rows 0..63) --------
__global__ void __launch_bounds__(1024) sinkhorn_k(int N, int L) {
    int b = blockIdx.x;
    __shared__ float v[4096];
    __shared__ float u[72];
    int tid = threadIdx.x;
    int lane = tid & 31, warp = tid >> 5;
    const float NEG_INF = -INFINITY;
    float log_mu = -logf(65.0f);
    float log_nu = -logf((float)N);
    long zb = (long)b * N;

    for (int n = tid; n < N; n += 1024) v[n] = 0.f;
    if (tid < 72) u[tid] = 0.f;
    __syncthreads();

    for (int it = 0; it < 3; it++) {
        for (int k = warp; k < 65; k += 32) {
            float m = NEG_INF, s = 0.f;
            const float* zr = g_Z + (long)k * L + zb;
            for (int n = lane; n < N; n += 32) {
                float val = zr[n] + v[n];
                if (val > m) { s = s * __expf(m - val) + 1.f; m = val; }
                else          s += __expf(val - m);
            }
#pragma unroll
            for (int off = 16; off; off >>= 1) {
                float m2 = __shfl_xor_sync(0xffffffffu, m, off);
                float s2 = __shfl_xor_sync(0xffffffffu, s, off);
                if (m2 > m) { s = s * __expf(m - m2) + s2; m = m2; }
                else if (m2 > NEG_INF) s += s2 * __expf(m2 - m);
            }
            if (lane == 0) u[k] = log_mu - (m + __logf(s));
        }
        __syncthreads();
        for (int n = tid; n < N; n += 1024) {
            float m = NEG_INF, s = 0.f;
            for (int k = 0; k < 65; k++) {
                float val = g_Z[(long)k * L + zb + n] + u[k];
                if (val > m) { s = s * __expf(m - val) + 1.f; m = val; }
                else          s += __expf(val - m);
            }
            v[n] = log_nu - (m + __logf(s));
        }
        __syncthreads();
    }
    for (int k = 0; k < 64; k++) {
        float uk = u[k];
        float* zr = g_Z + (long)k * L + zb;
        for (int n = tid; n < N; n += 1024) zr[n] = __expf(zr[n] + uk + v[n]);
    }
}

// -------- einsum: out[b,c,k] += sum_n feat[c,n] * P[k,n] --------
__global__ void __launch_bounds__(256) einsum_k(int scale, int N, int L) {
    int b = blockIdx.x;
    int nc0 = blockIdx.y * 128;
    __shared__ float Fs[32][132];
    __shared__ float Ps[32][68];
    int tid = threadIdx.x, tx = tid & 15, ty = tid >> 4;
    long base = (long)b * N;

    float acc[8][4];
#pragma unroll
    for (int i = 0; i < 8; i++)
#pragma unroll
        for (int j = 0; j < 4; j++) acc[i][j] = 0.f;

    for (int nc = nc0; nc < nc0 + 128; nc += 32) {
#pragma unroll
        for (int i = 0; i < 16; i++) {
            int e = tid + i * 256;
            int c = e >> 5, n = e & 31;
            Fs[n][c] = g_feat[(long)c * L + base + nc + n];
        }
#pragma unroll
        for (int i = 0; i < 8; i++) {
            int e = tid + i * 256;
            int k = e >> 5, n = e & 31;
            Ps[n][k] = g_Z[(long)k * L + base + nc + n];
        }
        __syncthreads();
#pragma unroll
        for (int kk = 0; kk < 32; kk++) {
            float a[8], bb[4];
            float4 t;
            t = *(const float4*)&Fs[kk][ty * 4];      a[0]=t.x; a[1]=t.y; a[2]=t.z; a[3]=t.w;
            t = *(const float4*)&Fs[kk][ty * 4 + 64]; a[4]=t.x; a[5]=t.y; a[6]=t.z; a[7]=t.w;
            t = *(const float4*)&Ps[kk][tx * 4];      bb[0]=t.x; bb[1]=t.y; bb[2]=t.z; bb[3]=t.w;
#pragma unroll
            for (int i = 0; i < 8; i++)
#pragma unroll
                for (int j = 0; j < 4; j++) acc[i][j] += a[i] * bb[j];
        }
        __syncthreads();
    }

    float* outp = g_out + ((long)scale * B_ + b) * (CDIM_ * KK_);
#pragma unroll
    for (int i = 0; i < 8; i++) {
        int r = (i < 4) ? (ty * 4 + i) : (64 + ty * 4 + i - 4);
#pragma unroll
        for (int j = 0; j < 4; j++)
            atomicAdd(&outp[r * 64 + tx * 4 + j], acc[i][j]);
    }
}

// -------- final normalization --------
__global__ void __launch_bounds__(256) final_k(float* __restrict__ out) {
    int b = blockIdx.x, tid = threadIdx.x;
    __shared__ float d[8192];
    __shared__ float cn[2][64];
    __shared__ float red[9];
    if (tid < 128) cn[tid >> 6][tid & 63] = 0.f;
    __syncthreads();
    const float* o0 = g_out + (long)b * 8192;
    const float* o1 = g_out + (long)(B_ + b) * 8192;
    for (int e = tid; e < 8192; e += 256) {
        float v0 = o0[e], v1 = o1[e];
        atomicAdd(&cn[0][e & 63], v0 * v0);
        atomicAdd(&cn[1][e & 63], v1 * v1);
    }
    __syncthreads();
    if (tid < 128) {
        float nn = sqrtf(cn[tid >> 6][tid & 63]);
        cn[tid >> 6][tid & 63] = 1.f / fmaxf(nn, 1e-12f);
    }
    __syncthreads();
    float ss = 0.f;
    for (int e = tid; e < 8192; e += 256) {
        int k = e & 63;
        float dv = 0.5f * (o0[e] * cn[0][k] + o1[e] * cn[1][k]);
        d[e] = dv;
        ss += dv * dv;
    }
#pragma unroll
    for (int off = 16; off; off >>= 1) ss += __shfl_xor_sync(0xffffffffu, ss, off);
    if ((tid & 31) == 0) red[tid >> 5] = ss;
    __syncthreads();
    if (tid == 0) {
        float t = 0.f;
        for (int i = 0; i < 8; i++) t += red[i];
        red[8] = 1.f / fmaxf(sqrtf(t), 1e-12f);
    }
    __syncthreads();
    float inv = red[8];
    for (int e = tid; e < 8192; e += 256) out[(long)b * 8192 + e] = d[e] * inv;
}

extern "C" void kernel_launch(void* const* d_in, const int* in_sizes, int n_in,
                              void* d_out, int out_size) {
    (void)in_sizes; (void)n_in; (void)out_size;
    const float* x = (const float*)d_in[0];

    zero_k<<<1024, 256>>>();
    transpose_k<<<(CIN * L0) / 256, 256>>>(x);
    pool_k<<<(CIN * L1) / 256, 256>>>(x);

    for (int s = 0; s < 2; s++) {
        int base = 1 + s * 12;
        const float* fw1 = (const float*)d_in[base + 0];
        const float* fb1 = (const float*)d_in[base + 1];
        const float* fw2 = (const float*)d_in[base + 2];
        const float* fb2 = (const float*)d_in[base + 3];
        const float* sw1 = (const float*)d_in[base + 4];
        const float* sb1 = (const float*)d_in[base + 5];
        const float* sw2 = (const float*)d_in[base + 6];
        const float* sb2 = (const float*)d_in[base + 7];
        const float* dw1 = (const float*)d_in[base + 8];
        const float* db1 = (const float*)d_in[base + 9];
        const float* dw2 = (const float*)d_in[base + 10];
        const float* db2 = (const float*)d_in[base + 11];

        int L = s ? L1 : L0;
        int N = s ? N1_ : N0_;
        int xid = s ? 1 : 0;

        // concat layer-1 weights, then one fused 1152-row GEMM (relu)
        concat1_k<<<1728, 256>>>(fw1, fb1, sw1, sb1, dw1, db1);
        tgemm<true><<<dim3(9, L / 128), 256>>>(nullptr, nullptr, xid, 0L, 2, 0L, 1152, CIN, L);
        // layer 2
        tgemm<false><<<dim3(1, L / 128), 256>>>(fw2, fb2, 2, 0L, 3, 0L, CDIM_, 512, L);
        tgemm<false><<<dim3(1, L / 128), 256>>>(sw2, sb2, 2, (long)512 * L, 4, 0L, KK_, 512, L);
        dustbin_k<<<L / 256, 256>>>(dw2, db2, L);

        sinkhorn_k<<<B_, 1024>>>(N, L);
        einsum_k<<<dim3(B_, N / 128), 256>>>(s, N, L);
    }

    final_k<<<B_, 256>>>((float*)d_out);
}

// round 3
// speedup vs baseline: 2.9253x; 1.2843x over previous
#include <cuda_runtime.h>
#include <math.h>

// Problem constants
#define B_    16
#define CIN   384
#define L0    65536   // B * 64*64
#define L1    16384   // B * 32*32
#define N0_   4096
#define N1_   1024
#define CDIM_ 128
#define KK_   64
#define BK    16

// weight buffer layout per scale: w1[1152*384] | w2f[128*512] | w2s[64*512]
#define W1SZ  (1152 * CIN)
#define W2FSZ (128 * 512)
#define W2SSZ (64 * 512)
#define WSTRIDE (W1SZ + W2FSZ + W2SSZ)

// -------- scratch (device globals; no allocation allowed) --------
__device__ float g_xt  [CIN * L0];        // x transposed, tf32-rounded [C, B*N0]
__device__ float g_x1t [CIN * L1];        // pooled x, tf32-rounded [C, B*N1]
__device__ float g_hidden[1152 * L0];     // relu(hidden), tf32-rounded
__device__ float g_feat[CDIM_ * L0];      // local_feat fp32 [128, L]
__device__ float g_Z   [65 * L0];         // E = exp(scores|dustbin) [65, L]
__device__ float g_out [2 * B_ * CDIM_ * KK_];
__device__ float g_wbuf[2 * WSTRIDE];     // tf32-rounded weights per scale
__device__ float g_bbuf[2 * 1152];        // layer-1 biases per scale
__device__ float g_c   [B_ * N0_];        // sinkhorn column scaling c_n

__device__ __forceinline__ float* bufptr(int id) {
    switch (id) {
        case 0: return g_xt;
        case 1: return g_x1t;
        case 2: return g_hidden;
        case 3: return g_feat;
        case 4: return g_Z;
        case 5: return g_wbuf;
        default: return g_bbuf;
    }
}

__device__ __forceinline__ float tf32r(float x) {
    unsigned u;
    asm("cvt.rna.tf32.f32 %0, %1;\n" : "=r"(u) : "f"(x));
    return __uint_as_float(u);
}

// -------- layout transforms (store tf32-rounded) --------
__global__ void transpose_k(const float* __restrict__ x) {
    int idx = blockIdx.x * 256 + threadIdx.x;
    int c = idx >> 16;
    int l = idx & 65535;
    int b = l >> 12;
    int n = l & 4095;
    g_xt[idx] = tf32r(x[((long)(b * CIN + c) << 12) + n]);
}

__global__ void pool_k(const float* __restrict__ x) {
    int idx = blockIdx.x * 256 + threadIdx.x;
    int c = idx >> 14;
    int l = idx & 16383;
    int b = l >> 10;
    int p = l & 1023;
    int i = p >> 5, j = p & 31;
    const float* xb = x + ((long)(b * CIN + c) << 12);
    int r0 = (2 * i) * 64 + 2 * j;
    g_x1t[idx] = tf32r(0.25f * (xb[r0] + xb[r0 + 1] + xb[r0 + 64] + xb[r0 + 65]));
}

__global__ void zero_k() {
    int i = blockIdx.x * 256 + threadIdx.x;
    if (i < 2 * B_ * CDIM_ * KK_) g_out[i] = 0.f;
}

// prep per-scale: concat+convert w1 weights, convert w2f/w2s, copy biases
__global__ void prep_k(int s,
                       const float* __restrict__ fw1, const float* __restrict__ fb1,
                       const float* __restrict__ sw1, const float* __restrict__ sb1,
                       const float* __restrict__ dw1, const float* __restrict__ db1,
                       const float* __restrict__ fw2, const float* __restrict__ sw2) {
    int idx = blockIdx.x * 256 + threadIdx.x;
    float* wb = g_wbuf + (long)s * WSTRIDE;
    const int A1 = 512 * CIN, A2 = 1024 * CIN;
    if (idx < W1SZ) {
        float v;
        if (idx < A1) v = fw1[idx];
        else if (idx < A2) v = sw1[idx - A1];
        else v = dw1[idx - A2];
        wb[idx] = tf32r(v);
    }
    if (idx < W2FSZ) wb[W1SZ + idx] = tf32r(fw2[idx]);
    if (idx < W2SSZ) wb[W1SZ + W2FSZ + idx] = tf32r(sw2[idx]);
    if (idx < 1152)
        g_bbuf[s * 1152 + idx] =
            (idx < 512) ? fb1[idx] : (idx < 1024) ? sb1[idx - 512] : db1[idx - 1024];
}

// -------- cp.async helpers --------
__device__ __forceinline__ void cp_async16(void* smem, const void* gmem, bool pred) {
    unsigned saddr = (unsigned)__cvta_generic_to_shared(smem);
    int sz = pred ? 16 : 0;
    asm volatile("cp.async.cg.shared.global [%0], [%1], 16, %2;\n"
                 :: "r"(saddr), "l"(gmem), "r"(sz));
}
__device__ __forceinline__ void cp_commit() { asm volatile("cp.async.commit_group;\n"); }
__device__ __forceinline__ void cp_wait0()  { asm volatile("cp.async.wait_group 0;\n"); }
__device__ __forceinline__ void cp_wait1()  { asm volatile("cp.async.wait_group 1;\n"); }

// -------- tf32 tensor-core GEMM (inputs pre-rounded to tf32 bits) --------
// MODE: 0 = plain fp32 store, 1 = relu + tf32-round store, 2 = exp store
template <int MODE>
__global__ void __launch_bounds__(256)
tgemm(long woff, const float* __restrict__ biasp, long boff,
      int xid, long xoff, int cid, long coff, int M, int K, int L) {
    const float* W = g_wbuf + woff;
    const float* bias = biasp ? biasp : (g_bbuf + boff);
    const float* X = bufptr(xid) + xoff;
    float* C = bufptr(cid) + coff;

    __shared__ float sA[2][128 * 20];
    __shared__ float sB[2][16 * 136];

    int tid = threadIdx.x;
    int lane = tid & 31, warp = tid >> 5;
    int wm = warp >> 1, wn = warp & 1;
    int g = lane >> 2, tg = lane & 3;
    int bm = blockIdx.x * 128, bl = blockIdx.y * 128;

    float acc[2][8][4];
#pragma unroll
    for (int mt = 0; mt < 2; mt++)
#pragma unroll
        for (int nt = 0; nt < 8; nt++)
#pragma unroll
            for (int i = 0; i < 4; i++) acc[mt][nt][i] = 0.f;

    int ntiles = K / BK;

#define PREFETCH(kt, buf)                                                          \
    {                                                                              \
        _Pragma("unroll")                                                          \
        for (int i = 0; i < 2; i++) {                                              \
            int f = tid + i * 256;                                                 \
            int m = f >> 2, kq = f & 3;                                            \
            int r = bm + m;                                                        \
            bool p = r < M;                                                        \
            int rs = p ? r : (M - 1);                                              \
            cp_async16(&sA[buf][m * 20 + kq * 4],                                  \
                       W + (long)rs * K + (kt) * BK + kq * 4, p);                  \
        }                                                                          \
        _Pragma("unroll")                                                          \
        for (int i = 0; i < 2; i++) {                                              \
            int f = tid + i * 256;                                                 \
            int k = f >> 5, nq = f & 31;                                           \
            cp_async16(&sB[buf][k * 136 + nq * 4],                                 \
                       X + (long)((kt) * BK + k) * L + bl + nq * 4, true);         \
        }                                                                          \
        cp_commit();                                                               \
    }

    PREFETCH(0, 0);

    for (int kt = 0; kt < ntiles; kt++) {
        int buf = kt & 1;
        if (kt + 1 < ntiles) {
            PREFETCH(kt + 1, buf ^ 1);
            cp_wait1();
        } else {
            cp_wait0();
        }
        __syncthreads();

        const float* A = sA[buf];
        const float* Bm = sB[buf];
#pragma unroll
        for (int ks = 0; ks < 2; ks++) {
            int k0 = ks * 8;
            unsigned a[2][4];
#pragma unroll
            for (int mt = 0; mt < 2; mt++) {
                int m0 = wm * 32 + mt * 16 + g;
                a[mt][0] = __float_as_uint(A[m0 * 20 + k0 + tg]);
                a[mt][1] = __float_as_uint(A[(m0 + 8) * 20 + k0 + tg]);
                a[mt][2] = __float_as_uint(A[m0 * 20 + k0 + tg + 4]);
                a[mt][3] = __float_as_uint(A[(m0 + 8) * 20 + k0 + tg + 4]);
            }
            unsigned bfr[8][2];
#pragma unroll
            for (int nt = 0; nt < 8; nt++) {
                int n0 = wn * 64 + nt * 8 + g;
                bfr[nt][0] = __float_as_uint(Bm[(k0 + tg) * 136 + n0]);
                bfr[nt][1] = __float_as_uint(Bm[(k0 + tg + 4) * 136 + n0]);
            }
#pragma unroll
            for (int mt = 0; mt < 2; mt++)
#pragma unroll
                for (int nt = 0; nt < 8; nt++) {
                    asm volatile(
                        "mma.sync.aligned.m16n8k8.row.col.f32.tf32.tf32.f32 "
                        "{%0,%1,%2,%3}, {%4,%5,%6,%7}, {%8,%9}, {%0,%1,%2,%3};\n"
                        : "+f"(acc[mt][nt][0]), "+f"(acc[mt][nt][1]),
                          "+f"(acc[mt][nt][2]), "+f"(acc[mt][nt][3])
                        : "r"(a[mt][0]), "r"(a[mt][1]), "r"(a[mt][2]), "r"(a[mt][3]),
                          "r"(bfr[nt][0]), "r"(bfr[nt][1]));
                }
        }
        __syncthreads();
    }
#undef PREFETCH

#pragma unroll
    for (int mt = 0; mt < 2; mt++) {
        int r0 = bm + wm * 32 + mt * 16 + g;
        int r1 = r0 + 8;
        float bv0 = (r0 < M) ? bias[r0] : 0.f;
        float bv1 = (r1 < M) ? bias[r1] : 0.f;
#pragma unroll
        for (int nt = 0; nt < 8; nt++) {
            int cc = bl + wn * 64 + nt * 8 + tg * 2;
            if (r0 < M) {
                float2 v;
                v.x = acc[mt][nt][0] + bv0;
                v.y = acc[mt][nt][1] + bv0;
                if (MODE == 1) { v.x = tf32r(fmaxf(v.x, 0.f)); v.y = tf32r(fmaxf(v.y, 0.f)); }
                if (MODE == 2) { v.x = __expf(v.x); v.y = __expf(v.y); }
                *(float2*)&C[(long)r0 * L + cc] = v;
            }
            if (r1 < M) {
                float2 v;
                v.x = acc[mt][nt][2] + bv1;
                v.y = acc[mt][nt][3] + bv1;
                if (MODE == 1) { v.x = tf32r(fmaxf(v.x, 0.f)); v.y = tf32r(fmaxf(v.y, 0.f)); }
                if (MODE == 2) { v.x = __expf(v.x); v.y = __expf(v.y); }
                *(float2*)&C[(long)r1 * L + cc] = v;
            }
        }
    }
}

// -------- dustbin: E[64, l] = exp(db2 + dw2 . hidden_d[:, l]) --------
__global__ void dustbin_k(const float* __restrict__ dw2, const float* __restrict__ db2, int L) {
    __shared__ float w[128];
    int tid = threadIdx.x;
    if (tid < 128) w[tid] = dw2[tid];
    __syncthreads();
    long l = (long)blockIdx.x * 256 + tid;
    const float* h = g_hidden + (long)1024 * L + l;
    float acc = db2[0];
#pragma unroll 8
    for (int k = 0; k < 128; k++) acc += w[k] * h[(long)k * L];
    g_Z[(long)64 * L + l] = __expf(acc);
}

// -------- Sinkhorn in exp space (3 iters), outputs c_n --------
__global__ void __launch_bounds__(1024) sinkhorn_k(int N, int L) {
    int b = blockIdx.x;
    __shared__ float c[4096];
    __shared__ float r[72];
    int tid = threadIdx.x;
    int lane = tid & 31, warp = tid >> 5;
    float mu = 1.0f / 65.0f;
    float nu = 1.0f / (float)N;
    long zb = (long)b * N;

    for (int n = tid; n < N; n += 1024) c[n] = 1.f;
    __syncthreads();

    for (int it = 0; it < 3; it++) {
        // r-step: warp per row k
        for (int k = warp; k < 65; k += 32) {
            float s = 0.f;
            const float* er = g_Z + (long)k * L + zb;
            for (int n = lane; n < N; n += 32) s += er[n] * c[n];
#pragma unroll
            for (int off = 16; off; off >>= 1) s += __shfl_xor_sync(0xffffffffu, s, off);
            if (lane == 0) r[k] = mu / s;
        }
        __syncthreads();
        // c-step: thread per column
        for (int n = tid; n < N; n += 1024) {
            float s = 0.f;
            const float* ec = g_Z + zb + n;
#pragma unroll 13
            for (int k = 0; k < 65; k++) s += ec[(long)k * L] * r[k];
            c[n] = nu / s;
        }
        __syncthreads();
    }
    for (int n = tid; n < N; n += 1024) g_c[zb + n] = c[n];
}

// -------- einsum: out[b,c,k] += sum_n feat[c,n] * E[k,n] * cn[n] --------
__global__ void __launch_bounds__(256) einsum_k(int scale, int N, int L) {
    int b = blockIdx.x;
    int nc0 = blockIdx.y * 128;
    __shared__ float Fs[32][132];
    __shared__ float Ps[32][68];
    int tid = threadIdx.x, tx = tid & 15, ty = tid >> 4;
    long base = (long)b * N;

    float acc[8][4];
#pragma unroll
    for (int i = 0; i < 8; i++)
#pragma unroll
        for (int j = 0; j < 4; j++) acc[i][j] = 0.f;

    for (int nc = nc0; nc < nc0 + 128; nc += 32) {
#pragma unroll
        for (int i = 0; i < 16; i++) {
            int e = tid + i * 256;
            int cch = e >> 5, n = e & 31;
            Fs[n][cch] = g_feat[(long)cch * L + base + nc + n];
        }
        {
            int n = tid & 31;
            float cv = g_c[base + nc + n];
#pragma unroll
            for (int i = 0; i < 8; i++) {
                int e = tid + i * 256;
                int k = e >> 5;
                Ps[n][k] = g_Z[(long)k * L + base + nc + n] * cv;
            }
        }
        __syncthreads();
#pragma unroll
        for (int kk = 0; kk < 32; kk++) {
            float a[8], bb[4];
            float4 t;
            t = *(const float4*)&Fs[kk][ty * 4];      a[0]=t.x; a[1]=t.y; a[2]=t.z; a[3]=t.w;
            t = *(const float4*)&Fs[kk][ty * 4 + 64]; a[4]=t.x; a[5]=t.y; a[6]=t.z; a[7]=t.w;
            t = *(const float4*)&Ps[kk][tx * 4];      bb[0]=t.x; bb[1]=t.y; bb[2]=t.z; bb[3]=t.w;
#pragma unroll
            for (int i = 0; i < 8; i++)
#pragma unroll
                for (int j = 0; j < 4; j++) acc[i][j] += a[i] * bb[j];
        }
        __syncthreads();
    }

    float* outp = g_out + ((long)scale * B_ + b) * (CDIM_ * KK_);
#pragma unroll
    for (int i = 0; i < 8; i++) {
        int rr = (i < 4) ? (ty * 4 + i) : (64 + ty * 4 + i - 4);
#pragma unroll
        for (int j = 0; j < 4; j++)
            atomicAdd(&outp[rr * 64 + tx * 4 + j], acc[i][j]);
    }
}

// -------- final normalization --------
__global__ void __launch_bounds__(256) final_k(float* __restrict__ out) {
    int b = blockIdx.x, tid = threadIdx.x;
    __shared__ float d[8192];
    __shared__ float cn[2][64];
    __shared__ float red[9];
    if (tid < 128) cn[tid >> 6][tid & 63] = 0.f;
    __syncthreads();
    const float* o0 = g_out + (long)b * 8192;
    const float* o1 = g_out + (long)(B_ + b) * 8192;
    for (int e = tid; e < 8192; e += 256) {
        float v0 = o0[e], v1 = o1[e];
        atomicAdd(&cn[0][e & 63], v0 * v0);
        atomicAdd(&cn[1][e & 63], v1 * v1);
    }
    __syncthreads();
    if (tid < 128) {
        float nn = sqrtf(cn[tid >> 6][tid & 63]);
        cn[tid >> 6][tid & 63] = 1.f / fmaxf(nn, 1e-12f);
    }
    __syncthreads();
    float ss = 0.f;
    for (int e = tid; e < 8192; e += 256) {
        int k = e & 63;
        float dv = 0.5f * (o0[e] * cn[0][k] + o1[e] * cn[1][k]);
        d[e] = dv;
        ss += dv * dv;
    }
#pragma unroll
    for (int off = 16; off; off >>= 1) ss += __shfl_xor_sync(0xffffffffu, ss, off);
    if ((tid & 31) == 0) red[tid >> 5] = ss;
    __syncthreads();
    if (tid == 0) {
        float t = 0.f;
        for (int i = 0; i < 8; i++) t += red[i];
        red[8] = 1.f / fmaxf(sqrtf(t), 1e-12f);
    }
    __syncthreads();
    float inv = red[8];
    for (int e = tid; e < 8192; e += 256) out[(long)b * 8192 + e] = d[e] * inv;
}

extern "C" void kernel_launch(void* const* d_in, const int* in_sizes, int n_in,
                              void* d_out, int out_size) {
    (void)in_sizes; (void)n_in; (void)out_size;
    const float* x = (const float*)d_in[0];

    // launch order chosen so launch #5 (ncu -s 5 -c 1) is the big L1 GEMM
    zero_k<<<1024, 256>>>();
    transpose_k<<<(CIN * L0) / 256, 256>>>(x);
    pool_k<<<(CIN * L1) / 256, 256>>>(x);
    for (int s = 0; s < 2; s++) {
        int base = 1 + s * 12;
        prep_k<<<1728, 256>>>(s,
            (const float*)d_in[base + 0], (const float*)d_in[base + 1],
            (const float*)d_in[base + 4], (const float*)d_in[base + 5],
            (const float*)d_in[base + 8], (const float*)d_in[base + 9],
            (const float*)d_in[base + 2], (const float*)d_in[base + 6]);
    }

    for (int s = 0; s < 2; s++) {
        int base = 1 + s * 12;
        const float* fb2 = (const float*)d_in[base + 3];
        const float* sb2 = (const float*)d_in[base + 7];
        const float* dw2 = (const float*)d_in[base + 10];
        const float* db2 = (const float*)d_in[base + 11];

        int L = s ? L1 : L0;
        int N = s ? N1_ : N0_;
        int xid = s ? 1 : 0;
        long ws = (long)s * WSTRIDE;

        // fused layer-1 (relu, tf32-rounded store)
        tgemm<1><<<dim3(9, L / 128), 256>>>(ws, nullptr, (long)s * 1152,
                                            xid, 0L, 2, 0L, 1152, CIN, L);
        // layer-2 feat (plain fp32)
        tgemm<0><<<dim3(1, L / 128), 256>>>(ws + W1SZ, fb2, 0L,
                                            2, 0L, 3, 0L, CDIM_, 512, L);
        // layer-2 score (exp store -> E)
        tgemm<2><<<dim3(1, L / 128), 256>>>(ws + W1SZ + W2FSZ, sb2, 0L,
                                            2, (long)512 * L, 4, 0L, KK_, 512, L);
        dustbin_k<<<L / 256, 256>>>(dw2, db2, L);

        sinkhorn_k<<<B_, 1024>>>(N, L);
        einsum_k<<<dim3(B_, N / 128), 256>>>(s, N, L);
    }

    final_k<<<B_, 256>>>((float*)d_out);
}